// round 7
// baseline (speedup 1.0000x reference)
#include <cuda_runtime.h>
#include <cstdint>
#include <cstdio>

// Problem shape (fixed by the dataset)
constexpr int B   = 8192;
constexpr int S   = 6;
constexpr int H   = 1024;
constexpr int H2  = 2048;

constexpr size_t OUT_W_OFF = (size_t)B * H;            // 8,388,608
constexpr size_t OUT_E_OFF = OUT_W_OFF + (size_t)B*S;  // 8,437,760

// ---------------- device scratch (no allocs allowed) ----------------
__device__ float g_cond [(size_t)B * H2];   // [B, 2H] : (mean | max)   64 MB
__device__ float g_A    [(size_t)H2 * H];   // Wq @ Wk^T                 8 MB
__device__ float g_kvec [(size_t)B * H];    // per-row key-projected q  32 MB
__device__ float g_ebar [(size_t)B * H];    // weighted-pooled evidence 32 MB
__device__ float g_kconst[H];
__device__ float g_kgate [H];
__device__ float g_u     [H2];
__device__ float g_c     [2];
__device__ float g_s0    [B];

__device__ __forceinline__ float warpSum(float v) {
#pragma unroll
    for (int o = 16; o > 0; o >>= 1) v += __shfl_xor_sync(0xffffffffu, v, o);
    return v;
}

// block-wide sum over 256 threads; result valid in thread 0
__device__ __forceinline__ float blockSum256(float v, float* sh, int lane, int warp, int t) {
    v = warpSum(v);
    if (lane == 0) sh[warp] = v;
    __syncthreads();
    float r = 0.f;
    if (t == 0) {
#pragma unroll
        for (int w = 0; w < 8; w++) r += sh[w];
    }
    __syncthreads();
    return r;
}

// ---------------- precompute folded vectors ----------------
// kconst[h] = sum_k Wk[h,k]*(bq[k]+bp[k]);  kgate[h] = sum_k Wk[h,k]*Wp[k]
// u[j]      = sum_k Wq[j,k]*bk[k];  c0 = bk·(bq+bp);  c1 = bk·Wp
__global__ void k_prevec(const float* __restrict__ Wk, const float* __restrict__ Wq,
                         const float* __restrict__ bk, const float* __restrict__ bq,
                         const float* __restrict__ bp, const float* __restrict__ Wp)
{
    __shared__ float sh[8];
    int bid = blockIdx.x, t = threadIdx.x, lane = t & 31, warp = t >> 5;

    if (bid < H) {
        const float* row = Wk + (size_t)bid * H;
        float a = 0.f, g = 0.f;
        for (int k = t; k < H; k += 256) {
            float w = row[k];
            a = fmaf(w, bq[k] + bp[k], a);
            g = fmaf(w, Wp[k], g);
        }
        float ra = blockSum256(a, sh, lane, warp, t);
        float rg = blockSum256(g, sh, lane, warp, t);
        if (t == 0) { g_kconst[bid] = ra; g_kgate[bid] = rg; }
    } else if (bid < H + H2) {
        int j = bid - H;
        const float* row = Wq + (size_t)j * H;
        float a = 0.f;
        for (int k = t; k < H; k += 256) a = fmaf(row[k], bk[k], a);
        float r = blockSum256(a, sh, lane, warp, t);
        if (t == 0) g_u[j] = r;
    } else {
        float a = 0.f, g = 0.f;
        for (int k = t; k < H; k += 256) {
            a = fmaf(bk[k], bq[k] + bp[k], a);
            g = fmaf(bk[k], Wp[k], g);
        }
        float ra = blockSum256(a, sh, lane, warp, t);
        float rg = blockSum256(g, sh, lane, warp, t);
        if (t == 0) { g_c[0] = ra; g_c[1] = rg; }
    }
}

// ---------------- pooling: cond = (mean|max), s0 = u·cond + c0 + gate*c1 ----------------
__global__ void k_pool(const float* __restrict__ E, const float* __restrict__ gate)
{
    int b = blockIdx.x, t = threadIdx.x, lane = t & 31, warp = t >> 5;
    __shared__ float sh[8];

    const float4* Eb = (const float4*)(E + (size_t)b * (S * H));
    float4 m = Eb[t];
    float4 mx = m;
#pragma unroll
    for (int s = 1; s < S; s++) {
        float4 v = Eb[s * 256 + t];
        m.x += v.x; m.y += v.y; m.z += v.z; m.w += v.w;
        mx.x = fmaxf(mx.x, v.x); mx.y = fmaxf(mx.y, v.y);
        mx.z = fmaxf(mx.z, v.z); mx.w = fmaxf(mx.w, v.w);
    }
    const float c = 1.f / 6.f;
    m.x *= c; m.y *= c; m.z *= c; m.w *= c;

    float4* condb = (float4*)(g_cond + (size_t)b * H2);
    condb[t]       = m;
    condb[256 + t] = mx;

    const float4* u4 = (const float4*)g_u;
    float4 ua = u4[t], ub = u4[256 + t];
    float p = m.x*ua.x + m.y*ua.y + m.z*ua.z + m.w*ua.w
            + mx.x*ub.x + mx.y*ub.y + mx.z*ub.z + mx.w*ub.w;
    p = warpSum(p);
    if (lane == 0) sh[warp] = p;
    __syncthreads();
    if (t == 0) {
        float r = 0.f;
#pragma unroll
        for (int w = 0; w < 8; w++) r += sh[w];
        g_s0[b] = r + g_c[0] + gate[b] * g_c[1];
    }
}

// ---------------- tiled SGEMM, double-buffered smem ----------------
// C[M,N] = Amat[M,K] * Bmat (+ epilogue)
// B_NN = 1 : Bmat is [K,N] row-major (n contiguous)
// B_NN = 0 : Bmat is [N,K] row-major (k contiguous)  -> C = A * B^T
// epilogue: C += rv[n] (if rv) + cv[m]*rv2[n] (if cv)
template<int B_NN>
__global__ void __launch_bounds__(256, 2)
k_sgemm(const float* __restrict__ Am, const float* __restrict__ Bm, float* __restrict__ Cm,
        int M, int N, int K,
        const float* __restrict__ rv, const float* __restrict__ cv, const float* __restrict__ rv2)
{
    constexpr int BM = 128, BN = 128, BK = 16;
    __shared__ __align__(16) float As[2][BK][BM];
    __shared__ __align__(16) float Bs[2][BK][BN];

    const int tid  = threadIdx.x;
    const int m0   = blockIdx.y * BM;
    const int n0   = blockIdx.x * BN;
    const int warp = tid >> 5, lane = tid & 31;
    // warp tile 32x64, lane tile 8x8
    const int row0 = (warp & 3) * 32 + (lane >> 3) * 8;
    const int col0 = (warp >> 2) * 64 + (lane & 7) * 8;

    float acc[8][8] = {};

    // tile loaders: LDG + STS into the given buffer (no sync inside)
    auto loadA = [&](int k0, int bf) {
#pragma unroll
        for (int l = 0; l < 2; l++) {
            int i  = tid + l * 256;          // 0..511
            int ar = i >> 2, akq = i & 3;
            float4 v = *(const float4*)(Am + (size_t)(m0 + ar) * K + k0 + akq * 4);
            As[bf][akq*4 + 0][ar] = v.x;
            As[bf][akq*4 + 1][ar] = v.y;
            As[bf][akq*4 + 2][ar] = v.z;
            As[bf][akq*4 + 3][ar] = v.w;
        }
    };
    auto loadB = [&](int k0, int bf) {
        if (B_NN) {
#pragma unroll
            for (int l = 0; l < 2; l++) {
                int i  = tid + l * 256;
                int bk_ = i >> 5, bnq = i & 31;
                float4 v = *(const float4*)(Bm + (size_t)(k0 + bk_) * N + n0 + bnq * 4);
                *(float4*)&Bs[bf][bk_][bnq * 4] = v;
            }
        } else {
#pragma unroll
            for (int l = 0; l < 2; l++) {
                int i  = tid + l * 256;
                int br = i >> 2, bkq = i & 3;
                float4 v = *(const float4*)(Bm + (size_t)(n0 + br) * K + k0 + bkq * 4);
                Bs[bf][bkq*4 + 0][br] = v.x;
                Bs[bf][bkq*4 + 1][br] = v.y;
                Bs[bf][bkq*4 + 2][br] = v.z;
                Bs[bf][bkq*4 + 3][br] = v.w;
            }
        }
    };

    int buf = 0;
    loadA(0, 0);
    loadB(0, 0);
    __syncthreads();

    for (int k0 = 0; k0 < K; k0 += BK) {
        // prefetch next slice into the inactive buffer (overlaps with compute below)
        int nk = k0 + BK;
        if (nk < K) {
            loadA(nk, buf ^ 1);
            loadB(nk, buf ^ 1);
        }

#pragma unroll
        for (int kk = 0; kk < BK; kk++) {
            float a[8], b[8];
            *(float4*)(a)     = *(const float4*)&As[buf][kk][row0];
            *(float4*)(a + 4) = *(const float4*)&As[buf][kk][row0 + 4];
            *(float4*)(b)     = *(const float4*)&Bs[buf][kk][col0];
            *(float4*)(b + 4) = *(const float4*)&Bs[buf][kk][col0 + 4];
#pragma unroll
            for (int i = 0; i < 8; i++)
#pragma unroll
                for (int j = 0; j < 8; j++)
                    acc[i][j] = fmaf(a[i], b[j], acc[i][j]);
        }
        __syncthreads();   // compute on buf finished AND stores to buf^1 finished
        buf ^= 1;
    }

    // epilogue + store
    float rvv[8];
#pragma unroll
    for (int j = 0; j < 8; j++) rvv[j] = rv ? rv[n0 + col0 + j] : 0.f;
    float rv2v[8];
#pragma unroll
    for (int j = 0; j < 8; j++) rv2v[j] = cv ? rv2[n0 + col0 + j] : 0.f;

#pragma unroll
    for (int i = 0; i < 8; i++) {
        int m = m0 + row0 + i;
        float cvm = cv ? cv[m] : 0.f;
        float4 o0, o1;
        o0.x = acc[i][0] + rvv[0] + cvm * rv2v[0];
        o0.y = acc[i][1] + rvv[1] + cvm * rv2v[1];
        o0.z = acc[i][2] + rvv[2] + cvm * rv2v[2];
        o0.w = acc[i][3] + rvv[3] + cvm * rv2v[3];
        o1.x = acc[i][4] + rvv[4] + cvm * rv2v[4];
        o1.y = acc[i][5] + rvv[5] + cvm * rv2v[5];
        o1.z = acc[i][6] + rvv[6] + cvm * rv2v[6];
        o1.w = acc[i][7] + rvv[7] + cvm * rv2v[7];
        *(float4*)(Cm + (size_t)m * N + n0 + col0)     = o0;
        *(float4*)(Cm + (size_t)m * N + n0 + col0 + 4) = o1;
    }
}

// ---------------- attend: scores -> softmax -> weights/entropy -> ebar ----------------
__global__ void k_attend(const float* __restrict__ E, const float* __restrict__ sb,
                         float* __restrict__ out)
{
    int b = blockIdx.x, t = threadIdx.x, lane = t & 31, warp = t >> 5;
    __shared__ __align__(16) float4 Es[S * 256];   // E_b, 24 KB
    __shared__ float part[S][8];
    __shared__ float wsh[8];

    const float4* Eb = (const float4*)(E + (size_t)b * (S * H));
    float4 kv = *((const float4*)(g_kvec + (size_t)b * H) + t);

    float acc[S];
#pragma unroll
    for (int s = 0; s < S; s++) {
        float4 e = Eb[s * 256 + t];
        Es[s * 256 + t] = e;
        acc[s] = e.x*kv.x + e.y*kv.y + e.z*kv.z + e.w*kv.w;
    }
#pragma unroll
    for (int s = 0; s < S; s++) {
        float v = warpSum(acc[s]);
        if (lane == 0) part[s][warp] = v;
    }
    __syncthreads();

    if (t == 0) {
        float sc[S];
        float mxv = -1e30f;
        float s0 = g_s0[b];
#pragma unroll
        for (int s = 0; s < S; s++) {
            float sum = 0.f;
#pragma unroll
            for (int w = 0; w < 8; w++) sum += part[s][w];
            sc[s] = sum + s0 + sb[s];
            mxv = fmaxf(mxv, sc[s]);
        }
        float Z = 0.f;
#pragma unroll
        for (int s = 0; s < S; s++) { sc[s] = expf(sc[s] - mxv); Z += sc[s]; }
        float inv = 1.f / Z;
        float ent = 0.f;
#pragma unroll
        for (int s = 0; s < S; s++) {
            float w = sc[s] * inv;
            wsh[s] = w;
            out[OUT_W_OFF + (size_t)b * S + s] = w;
            ent -= w * logf(w + 1e-8f);
        }
        out[OUT_E_OFF + b] = ent;
    }
    __syncthreads();

    float4 o = make_float4(0.f, 0.f, 0.f, 0.f);
#pragma unroll
    for (int s = 0; s < S; s++) {
        float w = wsh[s];
        float4 e = Es[s * 256 + t];
        o.x = fmaf(w, e.x, o.x); o.y = fmaf(w, e.y, o.y);
        o.z = fmaf(w, e.z, o.z); o.w = fmaf(w, e.w, o.w);
    }
    *((float4*)(g_ebar + (size_t)b * H) + t) = o;
}

// ---------------- launch ----------------
extern "C" void kernel_launch(void* const* d_in, const int* in_sizes, int n_in,
                              void* d_out, int out_size)
{
    const float* E    = (const float*)d_in[0];
    // d_in[1] = gene_context : unused by the reference
    const float* gate = (const float*)d_in[2];
    const float* Wk   = (const float*)d_in[3];
    const float* bk   = (const float*)d_in[4];
    const float* Wv   = (const float*)d_in[5];
    const float* bv   = (const float*)d_in[6];
    const float* Wq   = (const float*)d_in[7];
    const float* bq   = (const float*)d_in[8];
    const float* Wp   = (const float*)d_in[9];
    const float* bp   = (const float*)d_in[10];
    const float* sb   = (const float*)d_in[11];
    float* out = (float*)d_out;

    // device-global scratch addresses (host side must look them up)
    float *p_cond, *p_A, *p_kvec, *p_ebar, *p_kconst, *p_kgate;
    cudaGetSymbolAddress((void**)&p_cond,   g_cond);
    cudaGetSymbolAddress((void**)&p_A,      g_A);
    cudaGetSymbolAddress((void**)&p_kvec,   g_kvec);
    cudaGetSymbolAddress((void**)&p_ebar,   g_ebar);
    cudaGetSymbolAddress((void**)&p_kconst, g_kconst);
    cudaGetSymbolAddress((void**)&p_kgate,  g_kgate);

    // 1) folded vectors (kconst, kgate, u, c0/c1)
    k_prevec<<<H + H2 + 1, 256>>>(Wk, Wq, bk, bq, bp, Wp);

    // 2) A = Wq @ Wk^T   [2H, H]   (NT)
    {
        dim3 grid(H / 128, H2 / 128);
        k_sgemm<0><<<grid, 256>>>(Wq, Wk, p_A, H2, H, H, nullptr, nullptr, nullptr);
    }

    // 3) pooling -> cond, s0
    k_pool<<<B, 256>>>(E, gate);

    // 4) kvec = cond @ A + kconst + gate*kgate   [B, H]   (NN)
    {
        dim3 grid(H / 128, B / 128);
        k_sgemm<1><<<grid, 256>>>(p_cond, p_A, p_kvec, B, H, H2, p_kconst, gate, p_kgate);
    }

    // 5) scores/softmax/entropy/weighted pool
    k_attend<<<B, 256>>>(E, sb, out);

    // 6) fused = ebar @ Wv + bv  -> d_out[0 : B*H]   (NN)
    {
        dim3 grid(H / 128, B / 128);
        k_sgemm<1><<<grid, 256>>>(p_ebar, Wv, out, B, H, H, bv, nullptr, nullptr);
    }
}

// round 15
// speedup vs baseline: 1.6384x; 1.6384x over previous
#include <cuda_runtime.h>
#include <cuda_bf16.h>
#include <cstdint>

// Problem shape (fixed)
constexpr int B   = 8192;
constexpr int S   = 6;
constexpr int H   = 1024;
constexpr int H2  = 2048;
constexpr int K3  = 3 * H;    // 3072
constexpr int K6  = 3 * H2;   // 6144

constexpr size_t OUT_W_OFF = (size_t)B * H;
constexpr size_t OUT_E_OFF = OUT_W_OFF + (size_t)B * S;

// ---------------- device scratch (16B-aligned for uint4 loads) ----------------
__device__ __align__(16) __nv_bfloat16 g_Wkcat [(size_t)H  * K3];  // [hi|hi|lo]
__device__ __align__(16) __nv_bfloat16 g_Wqcat [(size_t)H2 * K3];  // [hi|lo|hi]
__device__ __align__(16) __nv_bfloat16 g_Wvcat [(size_t)H  * K3];  // [hi|hi|lo] (Wv^T)
__device__ __align__(16) __nv_bfloat16 g_Acat  [(size_t)H  * K6];  // [hi|hi|lo]
__device__ __align__(16) __nv_bfloat16 g_condcat[(size_t)B * K6];  // [chi|clo|chi]
__device__ __align__(16) __nv_bfloat16 g_ebarcat[(size_t)B * K3];  // [ehi|elo|ehi]
__device__ float g_kvec [(size_t)B * H];
__device__ float g_kconst[H];
__device__ float g_kgate [H];
__device__ float g_u     [H2];
__device__ float g_c     [2];
__device__ float g_s0    [B];

__device__ __forceinline__ void fsplit(float x, __nv_bfloat16& hi, __nv_bfloat16& lo) {
    hi = __float2bfloat16(x);
    lo = __float2bfloat16(x - __bfloat162float(hi));
}

__device__ __forceinline__ float warpSum(float v) {
#pragma unroll
    for (int o = 16; o > 0; o >>= 1) v += __shfl_xor_sync(0xffffffffu, v, o);
    return v;
}

__device__ __forceinline__ float blockSum256(float v, float* sh, int lane, int warp, int t) {
    v = warpSum(v);
    if (lane == 0) sh[warp] = v;
    __syncthreads();
    float r = 0.f;
    if (t == 0) {
#pragma unroll
        for (int w = 0; w < 8; w++) r += sh[w];
    }
    __syncthreads();
    return r;
}

// ---------------- weight split kernels ----------------
template<int MODE>   // 0: [hi|hi|lo]   1: [hi|lo|hi]
__global__ void k_split(const float* __restrict__ W, __nv_bfloat16* __restrict__ out,
                        int rows, int cols)
{
    int idx = blockIdx.x * 256 + threadIdx.x;
    if (idx >= rows * cols) return;
    int r = idx / cols, c = idx % cols;
    __nv_bfloat16 hi, lo; fsplit(W[idx], hi, lo);
    __nv_bfloat16* p = out + (size_t)r * 3 * cols;
    if (MODE == 0) { p[c] = hi; p[cols + c] = hi; p[2*cols + c] = lo; }
    else           { p[c] = hi; p[cols + c] = lo; p[2*cols + c] = hi; }
}

// transpose + split: Wvcat[n][k] from Wv[k][n], segs [hi|hi|lo]
__global__ void k_splitWvT(const float* __restrict__ Wv, __nv_bfloat16* __restrict__ out)
{
    int idx = blockIdx.x * 256 + threadIdx.x;
    if (idx >= H * H) return;
    int n = idx >> 10, k = idx & 1023;
    __nv_bfloat16 hi, lo; fsplit(Wv[(size_t)k * H + n], hi, lo);
    __nv_bfloat16* p = out + (size_t)n * K3;
    p[k] = hi; p[H + k] = hi; p[2*H + k] = lo;
}

// ---------------- precompute folded vectors (fp32) ----------------
__global__ void k_prevec(const float* __restrict__ Wk, const float* __restrict__ Wq,
                         const float* __restrict__ bk, const float* __restrict__ bq,
                         const float* __restrict__ bp, const float* __restrict__ Wp)
{
    __shared__ float sh[8];
    int bid = blockIdx.x, t = threadIdx.x, lane = t & 31, warp = t >> 5;

    if (bid < H) {
        const float* row = Wk + (size_t)bid * H;
        float a = 0.f, g = 0.f;
        for (int k = t; k < H; k += 256) {
            float w = row[k];
            a = fmaf(w, bq[k] + bp[k], a);
            g = fmaf(w, Wp[k], g);
        }
        float ra = blockSum256(a, sh, lane, warp, t);
        float rg = blockSum256(g, sh, lane, warp, t);
        if (t == 0) { g_kconst[bid] = ra; g_kgate[bid] = rg; }
    } else if (bid < H + H2) {
        int j = bid - H;
        const float* row = Wq + (size_t)j * H;
        float a = 0.f;
        for (int k = t; k < H; k += 256) a = fmaf(row[k], bk[k], a);
        float r = blockSum256(a, sh, lane, warp, t);
        if (t == 0) g_u[j] = r;
    } else {
        float a = 0.f, g = 0.f;
        for (int k = t; k < H; k += 256) {
            a = fmaf(bk[k], bq[k] + bp[k], a);
            g = fmaf(bk[k], Wp[k], g);
        }
        float ra = blockSum256(a, sh, lane, warp, t);
        float rg = blockSum256(g, sh, lane, warp, t);
        if (t == 0) { g_c[0] = ra; g_c[1] = rg; }
    }
}

// ---------------- pooling -> condcat (split bf16) + s0 ----------------
__global__ void k_pool(const float* __restrict__ E, const float* __restrict__ gate)
{
    int b = blockIdx.x, t = threadIdx.x, lane = t & 31, warp = t >> 5;
    __shared__ float sh[8];

    const float4* Eb = (const float4*)(E + (size_t)b * (S * H));
    float4 m = Eb[t];
    float4 mx = m;
#pragma unroll
    for (int s = 1; s < S; s++) {
        float4 v = Eb[s * 256 + t];
        m.x += v.x; m.y += v.y; m.z += v.z; m.w += v.w;
        mx.x = fmaxf(mx.x, v.x); mx.y = fmaxf(mx.y, v.y);
        mx.z = fmaxf(mx.z, v.z); mx.w = fmaxf(mx.w, v.w);
    }
    const float c = 1.f / 6.f;
    m.x *= c; m.y *= c; m.z *= c; m.w *= c;

    // split-write condcat: segments [chi(0..2H) | clo | chi], cond = (mean | max)
    {
        __nv_bfloat16* p = g_condcat + (size_t)b * K6;
        float mv[4] = {m.x, m.y, m.z, m.w};
        float xv[4] = {mx.x, mx.y, mx.z, mx.w};
#pragma unroll
        for (int j = 0; j < 4; j++) {
            __nv_bfloat16 hi, lo;
            int cc = t * 4 + j;          // mean index 0..1023
            fsplit(mv[j], hi, lo);
            p[cc] = hi; p[H2 + cc] = lo; p[2*H2 + cc] = hi;
            int cx = H + cc;             // max index 1024..2047
            fsplit(xv[j], hi, lo);
            p[cx] = hi; p[H2 + cx] = lo; p[2*H2 + cx] = hi;
        }
    }

    const float4* u4 = (const float4*)g_u;
    float4 ua = u4[t], ub = u4[256 + t];
    float p = m.x*ua.x + m.y*ua.y + m.z*ua.z + m.w*ua.w
            + mx.x*ub.x + mx.y*ub.y + mx.z*ub.z + mx.w*ub.w;
    p = warpSum(p);
    if (lane == 0) sh[warp] = p;
    __syncthreads();
    if (t == 0) {
        float r = 0.f;
#pragma unroll
        for (int w = 0; w < 8; w++) r += sh[w];
        g_s0[b] = r + g_c[0] + gate[b] * g_c[1];
    }
}

// ---------------- bf16 tensor-core GEMM (NT, both operands k-contiguous) ----------------
__device__ __forceinline__ void mma16816(float* c, const uint32_t* a, uint32_t b0, uint32_t b1) {
    asm volatile(
        "mma.sync.aligned.m16n8k16.row.col.f32.bf16.bf16.f32 "
        "{%0,%1,%2,%3},{%4,%5,%6,%7},{%8,%9},{%0,%1,%2,%3};"
        : "+f"(c[0]), "+f"(c[1]), "+f"(c[2]), "+f"(c[3])
        : "r"(a[0]), "r"(a[1]), "r"(a[2]), "r"(a[3]), "r"(b0), "r"(b1));
}

constexpr int SKP = 40;   // smem row stride in bf16 (pad 32->40: conflict-free frags)

template<int EPI>
__global__ __launch_bounds__(256, 2)
void k_bgemm(const __nv_bfloat16* __restrict__ Am, const __nv_bfloat16* __restrict__ Bm,
             float* __restrict__ Cf, __nv_bfloat16* __restrict__ Cb,
             int M, int N, int Kp,
             const float* __restrict__ rv, const float* __restrict__ cv,
             const float* __restrict__ rv2)
{
    __shared__ __align__(16) __nv_bfloat16 As[2][128 * SKP];
    __shared__ __align__(16) __nv_bfloat16 Bs[2][128 * SKP];

    const int tid  = threadIdx.x, lane = tid & 31, warp = tid >> 5;
    const int m0   = blockIdx.y * 128, n0 = blockIdx.x * 128;
    const int row0 = (warp & 3) * 32;       // 4 warps over M
    const int col0 = (warp >> 2) * 64;      // 2 warps over N
    const int lr   = lane >> 2, lc = (lane & 3) * 2;

    float acc[2][8][4] = {};

    auto loadT = [&](const __nv_bfloat16* G, int base, int k0, __nv_bfloat16* dst) {
#pragma unroll
        for (int l = 0; l < 2; l++) {
            int idx = tid + l * 256;               // 0..511
            int row = idx >> 2, cp = idx & 3;      // 128 rows x 4 16B-chunks
            *(uint4*)(dst + row * SKP + cp * 8) =
                *(const uint4*)(G + (size_t)(base + row) * Kp + k0 + cp * 8);
        }
    };

    int buf = 0;
    loadT(Am, m0, 0, As[0]);
    loadT(Bm, n0, 0, Bs[0]);
    __syncthreads();

    for (int k0 = 0; k0 < Kp; k0 += 32) {
        if (k0 + 32 < Kp) {
            loadT(Am, m0, k0 + 32, As[buf ^ 1]);
            loadT(Bm, n0, k0 + 32, Bs[buf ^ 1]);
        }
        const __nv_bfloat16* as = As[buf];
        const __nv_bfloat16* bs = Bs[buf];
#pragma unroll
        for (int ks = 0; ks < 2; ks++) {
            int kb = ks * 16 + lc;
            uint32_t a[2][4];
#pragma unroll
            for (int mt = 0; mt < 2; mt++) {
                int r = row0 + mt * 16 + lr;
                a[mt][0] = *(const uint32_t*)(as + r * SKP + kb);
                a[mt][1] = *(const uint32_t*)(as + (r + 8) * SKP + kb);
                a[mt][2] = *(const uint32_t*)(as + r * SKP + kb + 8);
                a[mt][3] = *(const uint32_t*)(as + (r + 8) * SKP + kb + 8);
            }
#pragma unroll
            for (int nt = 0; nt < 8; nt++) {
                int br = col0 + nt * 8 + lr;
                uint32_t b0 = *(const uint32_t*)(bs + br * SKP + kb);
                uint32_t b1 = *(const uint32_t*)(bs + br * SKP + kb + 8);
                mma16816(acc[0][nt], a[0], b0, b1);
                mma16816(acc[1][nt], a[1], b0, b1);
            }
        }
        __syncthreads();
        buf ^= 1;
    }

    // epilogue
#pragma unroll
    for (int mt = 0; mt < 2; mt++) {
#pragma unroll
        for (int nt = 0; nt < 8; nt++) {
            int r1 = m0 + row0 + mt * 16 + lr, r2 = r1 + 8;
            int c  = n0 + col0 + nt * 8 + lc;
            float v0 = acc[mt][nt][0], v1 = acc[mt][nt][1];
            float v2 = acc[mt][nt][2], v3 = acc[mt][nt][3];
            if (EPI == 0) {
                float a0 = rv ? rv[c] : 0.f, a1 = rv ? rv[c + 1] : 0.f;
                if (cv) {
                    float g1 = cv[r1], g2 = cv[r2];
                    float s0 = rv2[c], s1 = rv2[c + 1];
                    v0 += g1 * s0; v1 += g1 * s1;
                    v2 += g2 * s0; v3 += g2 * s1;
                }
                v0 += a0; v1 += a1; v2 += a0; v3 += a1;
                *(float2*)(Cf + (size_t)r1 * N + c) = make_float2(v0, v1);
                *(float2*)(Cf + (size_t)r2 * N + c) = make_float2(v2, v3);
            } else {
                __nv_bfloat16 h0, l0, h1, l1, h2, l2, h3, l3;
                fsplit(v0, h0, l0); fsplit(v1, h1, l1);
                fsplit(v2, h2, l2); fsplit(v3, h3, l3);
                __nv_bfloat16* p1 = Cb + (size_t)r1 * 3 * N;
                __nv_bfloat16* p2 = Cb + (size_t)r2 * 3 * N;
                *(__nv_bfloat162*)(p1 + c)         = __halves2bfloat162(h0, h1);
                *(__nv_bfloat162*)(p1 + N + c)     = __halves2bfloat162(h0, h1);
                *(__nv_bfloat162*)(p1 + 2*N + c)   = __halves2bfloat162(l0, l1);
                *(__nv_bfloat162*)(p2 + c)         = __halves2bfloat162(h2, h3);
                *(__nv_bfloat162*)(p2 + N + c)     = __halves2bfloat162(h2, h3);
                *(__nv_bfloat162*)(p2 + 2*N + c)   = __halves2bfloat162(l2, l3);
            }
        }
    }
}

// ---------------- attend: scores -> softmax -> weights/entropy -> ebarcat ----------------
__global__ void k_attend(const float* __restrict__ E, const float* __restrict__ sb,
                         float* __restrict__ out)
{
    int b = blockIdx.x, t = threadIdx.x, lane = t & 31, warp = t >> 5;
    __shared__ __align__(16) float4 Es[S * 256];
    __shared__ float part[S][8];
    __shared__ float wsh[8];

    const float4* Eb = (const float4*)(E + (size_t)b * (S * H));
    float4 kv = *((const float4*)(g_kvec + (size_t)b * H) + t);

    float acc[S];
#pragma unroll
    for (int s = 0; s < S; s++) {
        float4 e = Eb[s * 256 + t];
        Es[s * 256 + t] = e;
        acc[s] = e.x*kv.x + e.y*kv.y + e.z*kv.z + e.w*kv.w;
    }
#pragma unroll
    for (int s = 0; s < S; s++) {
        float v = warpSum(acc[s]);
        if (lane == 0) part[s][warp] = v;
    }
    __syncthreads();

    if (t == 0) {
        float sc[S];
        float mxv = -1e30f;
        float s0 = g_s0[b];
#pragma unroll
        for (int s = 0; s < S; s++) {
            float sum = 0.f;
#pragma unroll
            for (int w = 0; w < 8; w++) sum += part[s][w];
            sc[s] = sum + s0 + sb[s];
            mxv = fmaxf(mxv, sc[s]);
        }
        float Z = 0.f;
#pragma unroll
        for (int s = 0; s < S; s++) { sc[s] = expf(sc[s] - mxv); Z += sc[s]; }
        float inv = 1.f / Z;
        float ent = 0.f;
#pragma unroll
        for (int s = 0; s < S; s++) {
            float w = sc[s] * inv;
            wsh[s] = w;
            out[OUT_W_OFF + (size_t)b * S + s] = w;
            ent -= w * logf(w + 1e-8f);
        }
        out[OUT_E_OFF + b] = ent;
    }
    __syncthreads();

    float4 o = make_float4(0.f, 0.f, 0.f, 0.f);
#pragma unroll
    for (int s = 0; s < S; s++) {
        float w = wsh[s];
        float4 e = Es[s * 256 + t];
        o.x = fmaf(w, e.x, o.x); o.y = fmaf(w, e.y, o.y);
        o.z = fmaf(w, e.z, o.z); o.w = fmaf(w, e.w, o.w);
    }
    // split-write ebarcat: [ehi | elo | ehi]
    {
        __nv_bfloat16* p = g_ebarcat + (size_t)b * K3;
        float ov[4] = {o.x, o.y, o.z, o.w};
#pragma unroll
        for (int j = 0; j < 4; j++) {
            __nv_bfloat16 hi, lo;
            int cc = t * 4 + j;
            fsplit(ov[j], hi, lo);
            p[cc] = hi; p[H + cc] = lo; p[2*H + cc] = hi;
        }
    }
}

// ---------------- launch ----------------
extern "C" void kernel_launch(void* const* d_in, const int* in_sizes, int n_in,
                              void* d_out, int out_size)
{
    const float* E    = (const float*)d_in[0];
    const float* gate = (const float*)d_in[2];
    const float* Wk   = (const float*)d_in[3];
    const float* bk   = (const float*)d_in[4];
    const float* Wv   = (const float*)d_in[5];
    const float* bv   = (const float*)d_in[6];
    const float* Wq   = (const float*)d_in[7];
    const float* bq   = (const float*)d_in[8];
    const float* Wp   = (const float*)d_in[9];
    const float* bp   = (const float*)d_in[10];
    const float* sb   = (const float*)d_in[11];
    float* out = (float*)d_out;

    __nv_bfloat16 *p_Wkcat, *p_Wqcat, *p_Wvcat, *p_Acat, *p_condcat, *p_ebarcat;
    float *p_kvec, *p_kconst, *p_kgate;
    cudaGetSymbolAddress((void**)&p_Wkcat,   g_Wkcat);
    cudaGetSymbolAddress((void**)&p_Wqcat,   g_Wqcat);
    cudaGetSymbolAddress((void**)&p_Wvcat,   g_Wvcat);
    cudaGetSymbolAddress((void**)&p_Acat,    g_Acat);
    cudaGetSymbolAddress((void**)&p_condcat, g_condcat);
    cudaGetSymbolAddress((void**)&p_ebarcat, g_ebarcat);
    cudaGetSymbolAddress((void**)&p_kvec,    g_kvec);
    cudaGetSymbolAddress((void**)&p_kconst,  g_kconst);
    cudaGetSymbolAddress((void**)&p_kgate,   g_kgate);

    // 1) weight splits + folded vectors
    k_split<0><<<(H * H  + 255) / 256, 256>>>(Wk, p_Wkcat, H,  H);
    k_split<1><<<(H2 * H + 255) / 256, 256>>>(Wq, p_Wqcat, H2, H);
    k_splitWvT<<<(H * H + 255) / 256, 256>>>(Wv, p_Wvcat);
    k_prevec<<<H + H2 + 1, 256>>>(Wk, Wq, bk, bq, bp, Wp);

    // 2) T = Wk @ Wq^T  [H, 2H]  -> Acat (split epilogue)
    k_bgemm<1><<<dim3(H2 / 128, H / 128), 256>>>(
        p_Wkcat, p_Wqcat, nullptr, p_Acat, H, H2, K3, nullptr, nullptr, nullptr);

    // 3) pooling -> condcat, s0
    k_pool<<<B, 256>>>(E, gate);

    // 4) kvec = cond @ A + kconst + gate*kgate   [B, H]
    k_bgemm<0><<<dim3(H / 128, B / 128), 256>>>(
        p_condcat, p_Acat, p_kvec, nullptr, B, H, K6, p_kconst, gate, p_kgate);

    // 5) scores/softmax/entropy/weighted pool -> ebarcat
    k_attend<<<B, 256>>>(E, sb, out);

    // 6) fused = ebar @ Wv + bv  -> d_out[0 : B*H]
    k_bgemm<0><<<dim3(H / 128, B / 128), 256>>>(
        p_ebarcat, p_Wvcat, out, nullptr, B, H, K3, bv, nullptr, nullptr);
}